// round 5
// baseline (speedup 1.0000x reference)
#include <cuda_runtime.h>
#include <cuda_bf16.h>
#include <math.h>

#define NN 90000
#define PRE_K 6000
#define POST_K 300
#define NW 188                    // ceil(6000/32)
#define NBINS 65536
#define CAND_CAP 8192
#define MIN_SIZE 0.02f
#define GRID 148
#define BLK 256
#define STRIDE (GRID * BLK)
#define NSEG 8
#define SEG (CAND_CAP / NSEG)     // 1024
#define RB ((PRE_K + BLK - 1) / BLK)   // 24 row-blocks for matrix phase

// ---------------- device scratch ----------------
__device__ unsigned long long g_keys[NN];
__device__ float4             g_boxes[NN];
__device__ unsigned int       g_hist[NBINS];
__device__ unsigned long long g_cand[CAND_CAP];
__device__ int                g_cand_cnt;
__device__ unsigned int       g_thresh;
__device__ int                g_rank[CAND_CAP];
__device__ float4             g_top[PRE_K + 32];
__device__ unsigned int       g_valid[NW];
__device__ unsigned int       g_maskT[NW * PRE_K];   // [word][row]; lower-tri never written
__device__ unsigned int       g_barrier;

// ---------------- software grid barrier (all 148 blocks co-resident) ------
__device__ __forceinline__ void gsync(unsigned int target) {
    __syncthreads();
    if (threadIdx.x == 0) {
        __threadfence();
        atomicAdd(&g_barrier, 1u);
        volatile unsigned int* p = &g_barrier;
        while (*p < target) __nanosleep(64);
        __threadfence();
    }
    __syncthreads();
}

// ---------------- init kernel ----------------
__global__ void init_kernel() {
    int i = blockIdx.x * blockDim.x + threadIdx.x;
    for (int b = i; b < NBINS; b += 296 * 256) g_hist[b] = 0u;
    if (i < CAND_CAP) g_rank[i] = 0;
    if (i < NW) g_valid[i] = 0u;
    if (i == 0) { g_cand_cnt = 0; g_barrier = 0u; }
}

// ---------------- mega kernel ----------------
__global__ void __launch_bounds__(BLK, 1) mega_kernel(
        const float* __restrict__ pred_cls,
        const float* __restrict__ pred_reg,
        const float* __restrict__ anchor,
        float* __restrict__ out) {
    int tid = threadIdx.x;
    int bid = blockIdx.x;
    int gtid = bid * BLK + tid;

    __shared__ union {
        struct {                                    // thresh
            unsigned int part[256];
            unsigned int fine[256];
            int pt;
            unsigned int acc0;
        } th;
        unsigned long long tile[256];               // rank
        struct {                                    // matrix
            float4 cbox[32];
            float  carea[32];
        } mx;
        struct {                                    // serial
            unsigned int sup[NW];
            unsigned int svalid[NW];
            unsigned int cm[32 * NW];
            float4 sbox[32];
        } se;
    } sm;

    // ---------- phase 1: decode ----------
    for (int n = gtid; n < NN; n += STRIDE) {
        float4 a = *(const float4*)&anchor[n * 4];
        float4 r = *(const float4*)&pred_reg[n * 4];
        float acx = (a.x + a.z) * 0.5f;
        float acy = (a.y + a.w) * 0.5f;
        float aw  = a.z - a.x;
        float ah  = a.w - a.y;
        float cx = r.x * aw + acx;
        float cy = r.y * ah + acy;
        float w  = expf(r.z) * aw;
        float h  = expf(r.w) * ah;
        float x0 = fminf(fmaxf(cx - w * 0.5f, 0.f), 1.f);
        float y0 = fminf(fmaxf(cy - h * 0.5f, 0.f), 1.f);
        float x1 = fminf(fmaxf(cx + w * 0.5f, 0.f), 1.f);
        float y1 = fminf(fmaxf(cy + h * 0.5f, 0.f), 1.f);
        g_boxes[n] = make_float4(x0, y0, x1, y1);

        float l0 = pred_cls[2 * n];
        float l1 = pred_cls[2 * n + 1];
        float m  = fmaxf(l0, l1);
        float e0 = expf(l0 - m);
        float e1 = expf(l1 - m);
        float p  = e1 / (e0 + e1);
        bool size_ok = ((y1 - y0) >= MIN_SIZE) && ((x1 - x0) >= MIN_SIZE);
        float s = size_ok ? p : -INFINITY;
        unsigned int ub = __float_as_uint(s);
        unsigned int ordered = (ub & 0x80000000u) ? ~ub : (ub | 0x80000000u);
        unsigned long long key =
            ((unsigned long long)ordered << 17) | ((~(unsigned int)n) & 0x1FFFFu);
        g_keys[n] = key;
        atomicAdd(&g_hist[ordered >> 16], 1u);
    }
    gsync(1 * GRID);

    // ---------- phase 2: threshold (block 0) ----------
    if (bid == 0) {
        unsigned int s = 0;
        int base = tid * 256;
        for (int b = 0; b < 256; b++) s += g_hist[base + b];
        sm.th.part[tid] = s;
        __syncthreads();
        // suffix scan over coarse blocks
        for (int off = 1; off < 256; off <<= 1) {
            unsigned int v = (tid + off < 256) ? sm.th.part[tid + off] : 0u;
            __syncthreads();
            sm.th.part[tid] += v;
            __syncthreads();
        }
        // pt = max t with suffix(t) >= PRE_K
        bool pred = sm.th.part[tid] >= (unsigned)PRE_K;
        bool next = (tid < 255) ? (sm.th.part[tid + 1] >= (unsigned)PRE_K) : false;
        if (tid == 0) sm.th.pt = 0;                    // fallback (can't trigger: N >= PRE_K)
        __syncthreads();
        if (pred && !next) {
            sm.th.pt = tid;
            sm.th.acc0 = (tid < 255) ? sm.th.part[tid + 1] : 0u;
        }
        __syncthreads();
        int pt = sm.th.pt;
        unsigned int acc0 = sm.th.acc0;
        // fine suffix within coarse block pt
        sm.th.fine[tid] = g_hist[pt * 256 + tid];
        __syncthreads();
        for (int off = 1; off < 256; off <<= 1) {
            unsigned int v = (tid + off < 256) ? sm.th.fine[tid + off] : 0u;
            __syncthreads();
            sm.th.fine[tid] += v;
            __syncthreads();
        }
        bool fp = (acc0 + sm.th.fine[tid]) >= (unsigned)PRE_K;
        bool fn = (tid < 255) ? ((acc0 + sm.th.fine[tid + 1]) >= (unsigned)PRE_K) : false;
        if (fp && !fn) g_thresh = (unsigned int)(pt * 256 + tid);
    }
    gsync(2 * GRID);

    // ---------- phase 3: compact ----------
    {
        unsigned int T = g_thresh;
        for (int n = gtid; n < NN; n += STRIDE) {
            unsigned long long key = g_keys[n];
            if ((unsigned int)(key >> 33) >= T) {
                int p = atomicAdd(&g_cand_cnt, 1);
                if (p < CAND_CAP) g_cand[p] = key;
            }
        }
    }
    gsync(3 * GRID);

    // ---------- phase 4: rank by counting ----------
    {
        int C = g_cand_cnt; if (C > CAND_CAP) C = CAND_CAP;
        for (int pair = bid; pair < (CAND_CAP / 256) * NSEG; pair += GRID) {
            int bx  = pair / NSEG;
            int seg = pair % NSEG;
            int c   = bx * 256 + tid;
            unsigned long long kc = (c < C) ? g_cand[c] : 0xFFFFFFFFFFFFFFFFULL;
            int seg0 = seg * SEG;
            int cnt  = 0;
            for (int t0 = seg0; t0 < seg0 + SEG; t0 += 256) {
                int gi = t0 + tid;
                __syncthreads();
                sm.tile[tid] = (gi < C) ? g_cand[gi] : 0ULL;
                __syncthreads();
                #pragma unroll 8
                for (int k = 0; k < 256; k++)
                    cnt += (sm.tile[k] > kc);
            }
            if (c < C && cnt) atomicAdd(&g_rank[c], cnt);
        }
    }
    gsync(4 * GRID);

    // ---------- phase 5: scatter ----------
    {
        int C = g_cand_cnt; if (C > CAND_CAP) C = CAND_CAP;
        for (int c = gtid; c < C; c += STRIDE) {
            int rank = g_rank[c];
            if (rank >= PRE_K) continue;
            unsigned long long key = g_cand[c];
            unsigned int idx = (~(unsigned int)key) & 0x1FFFFu;
            float4 b = (idx < NN) ? g_boxes[idx] : make_float4(0.f, 0.f, 0.f, 0.f);
            g_top[rank] = b;
            if ((key >> 48) & 1ULL)
                atomicOr(&g_valid[rank >> 5], 1u << (rank & 31));
        }
    }
    gsync(5 * GRID);

    // ---------- phase 6: suppression matrix (upper triangle) ----------
    for (int t = bid; t < RB * NW; t += GRID) {
        int rb = t / NW;
        int w  = t % NW;
        int r0 = rb * BLK;
        int jbase = w * 32;
        if (jbase + 31 <= r0) continue;              // uniform per block
        __syncthreads();
        if (tid < 32) {
            int cc = jbase + tid;
            float4 b = (cc < PRE_K) ? g_top[cc] : make_float4(0.f, 0.f, 0.f, 0.f);
            sm.mx.cbox[tid]  = b;
            sm.mx.carea[tid] = (b.z - b.x) * (b.w - b.y);
        }
        __syncthreads();
        int r = r0 + tid;
        if (r < PRE_K && jbase + 31 > r) {
            float4 bi = g_top[r];
            float  ai = (bi.z - bi.x) * (bi.w - bi.y);
            unsigned int word = 0;
            #pragma unroll
            for (int k = 0; k < 32; k++) {
                int j = jbase + k;
                float4 bj = sm.mx.cbox[k];
                float x0 = fmaxf(bi.x, bj.x);
                float y0 = fmaxf(bi.y, bj.y);
                float x1 = fminf(bi.z, bj.z);
                float y1 = fminf(bi.w, bj.w);
                float iw = fmaxf(x1 - x0, 0.f);
                float ih = fmaxf(y1 - y0, 0.f);
                float inter = iw * ih;
                float u     = ai + sm.mx.carea[k] - inter;
                float um    = fmaxf(u, 1e-12f);
                float tt    = 0.7f * um;
                float d     = inter - tt;
                bool sup;
                if (fabsf(d) <= 1e-5f * tt)
                    sup = (inter / um) > 0.7f;
                else
                    sup = d > 0.f;
                if (sup && j > r && j < PRE_K) word |= (1u << k);
            }
            g_maskT[w * PRE_K + r] = word;
        }
    }
    gsync(6 * GRID);

    // ---------- phase 7: serial greedy NMS (block 0) ----------
    if (bid != 0) return;

    for (int i = tid; i < NW; i += BLK) { sm.se.sup[i] = 0u; sm.se.svalid[i] = g_valid[i]; }
    __syncthreads();

    int kept = 0;
    for (int c = 0; c * 32 < PRE_K && kept < POST_K; c++) {
        int r0 = c * 32;
        int rmax = min(32, PRE_K - r0);
        for (int idx = tid; idx < NW * 32; idx += BLK) {
            int w  = idx >> 5;
            int rl = idx & 31;
            sm.se.cm[rl * NW + w] = (rl < rmax) ? g_maskT[w * PRE_K + r0 + rl] : 0u;
        }
        if (tid < 32) sm.se.sbox[tid] = (tid < rmax) ? g_top[r0 + tid]
                                                     : make_float4(0.f, 0.f, 0.f, 0.f);
        __syncthreads();

        for (int rl = 0; rl < rmax; rl++) {
            int i = r0 + rl;
            bool keep = ((sm.se.svalid[i >> 5] >> (i & 31)) & 1u) &&
                        !((sm.se.sup[i >> 5] >> (i & 31)) & 1u);
            if (keep) {
                if (tid == 0) ((float4*)out)[kept] = sm.se.sbox[rl];
                if (tid < NW) sm.se.sup[tid] |= sm.se.cm[rl * NW + tid];
                __syncthreads();
                kept++;
                if (kept >= POST_K) break;
            }
        }
        __syncthreads();
    }

    for (int idx = tid; idx < (POST_K - kept) * 4; idx += BLK)
        out[kept * 4 + idx] = 0.f;
}

// ---------------- launcher ----------------
extern "C" void kernel_launch(void* const* d_in, const int* in_sizes, int n_in,
                              void* d_out, int out_size) {
    const float* pred_cls = (const float*)d_in[0];
    const float* pred_reg = (const float*)d_in[1];
    const float* anchor   = (const float*)d_in[2];
    float* out = (float*)d_out;

    init_kernel<<<296, 256>>>();
    mega_kernel<<<GRID, BLK>>>(pred_cls, pred_reg, anchor, out);
}

// round 6
// speedup vs baseline: 1.1281x; 1.1281x over previous
#include <cuda_runtime.h>
#include <cuda_bf16.h>
#include <math.h>

#define NN 90000
#define PRE_K 6000
#define POST_K 300
#define NW 188                    // ceil(6000/32)
#define NBINS 65536
#define CAND_CAP 8192
#define MIN_SIZE 0.02f
#define GRID 148
#define BLK 1024
#define STRIDE (GRID * BLK)
#define NSEG 16
#define SEG (CAND_CAP / NSEG)     // 512
#define CBX (CAND_CAP / BLK)      // 8 candidate x-units
#define RB ((PRE_K + BLK - 1) / BLK)   // 6 row-blocks for matrix phase

// ---------------- device scratch ----------------
__device__ unsigned long long g_keys[NN];
__device__ float4             g_boxes[NN];
__device__ unsigned int       g_hist[NBINS];
__device__ unsigned long long g_cand[CAND_CAP];
__device__ int                g_cand_cnt;
__device__ unsigned int       g_thresh;
__device__ int                g_rank[CAND_CAP];
__device__ float4             g_top[PRE_K + 32];
__device__ unsigned int       g_valid[NW];
__device__ unsigned int       g_maskT[NW * PRE_K];   // [word][row]; lower-tri never written
__device__ unsigned int       g_barrier;

// ---------------- software grid barrier (148 blocks, all co-resident) ------
__device__ __forceinline__ void gsync(unsigned int target) {
    __syncthreads();
    if (threadIdx.x == 0) {
        __threadfence();
        atomicAdd(&g_barrier, 1u);
        volatile unsigned int* p = &g_barrier;
        while (*p < target) __nanosleep(64);
        __threadfence();
    }
    __syncthreads();
}

// ---------------- init kernel ----------------
__global__ void init_kernel() {
    int i = blockIdx.x * blockDim.x + threadIdx.x;
    for (int b = i; b < NBINS; b += 296 * 256) g_hist[b] = 0u;
    if (i < CAND_CAP) g_rank[i] = 0;
    if (i < NW) g_valid[i] = 0u;
    if (i == 0) { g_cand_cnt = 0; g_barrier = 0u; }
}

// ---------------- mega kernel ----------------
__global__ void __launch_bounds__(BLK, 1) mega_kernel(
        const float* __restrict__ pred_cls,
        const float* __restrict__ pred_reg,
        const float* __restrict__ anchor,
        float* __restrict__ out) {
    int tid = threadIdx.x;
    int bid = blockIdx.x;
    int gtid = bid * BLK + tid;

    __shared__ union {
        struct {                                    // thresh
            unsigned int part[BLK];
            unsigned int fine[64];
            int pt;
            unsigned int acc0;
        } th;
        unsigned long long tile[SEG];               // rank
        struct {                                    // matrix
            float4 cbox[32];
            float  carea[32];
        } mx;
        struct {                                    // serial
            unsigned int sup[NW];
            unsigned int svalid[NW];
            unsigned int cm[32 * NW];
            float4 sbox[32];
        } se;
    } sm;

    // ---------- phase 1: decode ----------
    for (int n = gtid; n < NN; n += STRIDE) {
        float4 a = *(const float4*)&anchor[n * 4];
        float4 r = *(const float4*)&pred_reg[n * 4];
        float acx = (a.x + a.z) * 0.5f;
        float acy = (a.y + a.w) * 0.5f;
        float aw  = a.z - a.x;
        float ah  = a.w - a.y;
        float cx = r.x * aw + acx;
        float cy = r.y * ah + acy;
        float w  = expf(r.z) * aw;
        float h  = expf(r.w) * ah;
        float x0 = fminf(fmaxf(cx - w * 0.5f, 0.f), 1.f);
        float y0 = fminf(fmaxf(cy - h * 0.5f, 0.f), 1.f);
        float x1 = fminf(fmaxf(cx + w * 0.5f, 0.f), 1.f);
        float y1 = fminf(fmaxf(cy + h * 0.5f, 0.f), 1.f);
        g_boxes[n] = make_float4(x0, y0, x1, y1);

        float l0 = pred_cls[2 * n];
        float l1 = pred_cls[2 * n + 1];
        float m  = fmaxf(l0, l1);
        float e0 = expf(l0 - m);
        float e1 = expf(l1 - m);
        float p  = e1 / (e0 + e1);
        bool size_ok = ((y1 - y0) >= MIN_SIZE) && ((x1 - x0) >= MIN_SIZE);
        float s = size_ok ? p : -INFINITY;
        unsigned int ub = __float_as_uint(s);
        unsigned int ordered = (ub & 0x80000000u) ? ~ub : (ub | 0x80000000u);
        unsigned long long key =
            ((unsigned long long)ordered << 17) | ((~(unsigned int)n) & 0x1FFFFu);
        g_keys[n] = key;
        atomicAdd(&g_hist[ordered >> 16], 1u);
    }
    gsync(1 * GRID);

    // ---------- phase 2: threshold (block 0, 1024 threads) ----------
    if (bid == 0) {
        unsigned int s = 0;
        int base = tid * (NBINS / BLK);             // 64 bins per thread
        #pragma unroll 4
        for (int b = 0; b < NBINS / BLK; b++) s += g_hist[base + b];
        sm.th.part[tid] = s;
        __syncthreads();
        for (int off = 1; off < BLK; off <<= 1) {   // suffix scan
            unsigned int v = (tid + off < BLK) ? sm.th.part[tid + off] : 0u;
            __syncthreads();
            sm.th.part[tid] += v;
            __syncthreads();
        }
        bool pred = sm.th.part[tid] >= (unsigned)PRE_K;
        bool next = (tid < BLK - 1) ? (sm.th.part[tid + 1] >= (unsigned)PRE_K) : false;
        if (tid == 0) { sm.th.pt = 0; sm.th.acc0 = 0u; }
        __syncthreads();
        if (pred && !next) {
            sm.th.pt = tid;
            sm.th.acc0 = (tid < BLK - 1) ? sm.th.part[tid + 1] : 0u;
        }
        __syncthreads();
        int pt = sm.th.pt;
        unsigned int acc0 = sm.th.acc0;
        if (tid < 64) sm.th.fine[tid] = g_hist[pt * 64 + tid];
        __syncthreads();
        for (int off = 1; off < 64; off <<= 1) {
            unsigned int v = (tid < 64 && tid + off < 64) ? sm.th.fine[tid + off] : 0u;
            __syncthreads();
            if (tid < 64) sm.th.fine[tid] += v;
            __syncthreads();
        }
        if (tid < 64) {
            bool fp = (acc0 + sm.th.fine[tid]) >= (unsigned)PRE_K;
            bool fn = (tid < 63) ? ((acc0 + sm.th.fine[tid + 1]) >= (unsigned)PRE_K) : false;
            if (fp && !fn) g_thresh = (unsigned int)(pt * 64 + tid);
        }
    }
    gsync(2 * GRID);

    // ---------- phase 3: compact ----------
    {
        unsigned int T = g_thresh;
        for (int n = gtid; n < NN; n += STRIDE) {
            unsigned long long key = g_keys[n];
            if ((unsigned int)(key >> 33) >= T) {
                int p = atomicAdd(&g_cand_cnt, 1);
                if (p < CAND_CAP) g_cand[p] = key;
            }
        }
    }
    gsync(3 * GRID);

    // ---------- phase 4: rank by counting (keys unique) ----------
    {
        int C = g_cand_cnt; if (C > CAND_CAP) C = CAND_CAP;
        for (int unit = bid; unit < CBX * NSEG; unit += GRID) {
            int bx  = unit / NSEG;
            int seg = unit % NSEG;
            int c   = bx * BLK + tid;
            unsigned long long kc = (c < C) ? g_cand[c] : 0xFFFFFFFFFFFFFFFFULL;
            __syncthreads();
            if (tid < SEG) {
                int gi = seg * SEG + tid;
                sm.tile[tid] = (gi < C) ? g_cand[gi] : 0ULL;
            }
            __syncthreads();
            int cnt = 0;
            #pragma unroll 8
            for (int k = 0; k < SEG; k++)
                cnt += (sm.tile[k] > kc);
            if (c < C && cnt) atomicAdd(&g_rank[c], cnt);
        }
    }
    gsync(4 * GRID);

    // ---------- phase 5: scatter ----------
    {
        int C = g_cand_cnt; if (C > CAND_CAP) C = CAND_CAP;
        for (int c = gtid; c < C; c += STRIDE) {
            int rank = g_rank[c];
            if (rank >= PRE_K) continue;
            unsigned long long key = g_cand[c];
            unsigned int idx = (~(unsigned int)key) & 0x1FFFFu;
            float4 b = (idx < NN) ? g_boxes[idx] : make_float4(0.f, 0.f, 0.f, 0.f);
            g_top[rank] = b;
            if ((key >> 48) & 1ULL)
                atomicOr(&g_valid[rank >> 5], 1u << (rank & 31));
        }
    }
    gsync(5 * GRID);

    // ---------- phase 6: suppression matrix (upper triangle) ----------
    for (int t = bid; t < RB * NW; t += GRID) {
        int rb = t / NW;
        int w  = t % NW;
        int r0 = rb * BLK;
        int jbase = w * 32;
        if (jbase + 31 <= r0) continue;              // uniform per block
        __syncthreads();
        if (tid < 32) {
            int cc = jbase + tid;
            float4 b = (cc < PRE_K) ? g_top[cc] : make_float4(0.f, 0.f, 0.f, 0.f);
            sm.mx.cbox[tid]  = b;
            sm.mx.carea[tid] = (b.z - b.x) * (b.w - b.y);
        }
        __syncthreads();
        int r = r0 + tid;
        if (r < PRE_K && jbase + 31 > r) {
            float4 bi = g_top[r];
            float  ai = (bi.z - bi.x) * (bi.w - bi.y);
            unsigned int word = 0;
            #pragma unroll
            for (int k = 0; k < 32; k++) {
                int j = jbase + k;
                float4 bj = sm.mx.cbox[k];
                float x0 = fmaxf(bi.x, bj.x);
                float y0 = fmaxf(bi.y, bj.y);
                float x1 = fminf(bi.z, bj.z);
                float y1 = fminf(bi.w, bj.w);
                float iw = fmaxf(x1 - x0, 0.f);
                float ih = fmaxf(y1 - y0, 0.f);
                float inter = iw * ih;
                float u     = ai + sm.mx.carea[k] - inter;
                float um    = fmaxf(u, 1e-12f);
                float tt    = 0.7f * um;
                float d     = inter - tt;
                bool sup;
                if (fabsf(d) <= 1e-5f * tt)
                    sup = (inter / um) > 0.7f;
                else
                    sup = d > 0.f;
                if (sup && j > r && j < PRE_K) word |= (1u << k);
            }
            g_maskT[w * PRE_K + r] = word;
        }
    }
    gsync(6 * GRID);

    // ---------- phase 7: serial greedy NMS (block 0) ----------
    if (bid != 0) return;

    for (int i = tid; i < NW; i += BLK) { sm.se.sup[i] = 0u; sm.se.svalid[i] = g_valid[i]; }
    __syncthreads();

    int kept = 0;
    for (int c = 0; c * 32 < PRE_K && kept < POST_K; c++) {
        int r0 = c * 32;
        int rmax = min(32, PRE_K - r0);
        for (int idx = tid; idx < NW * 32; idx += BLK) {
            int w  = idx >> 5;
            int rl = idx & 31;
            sm.se.cm[rl * NW + w] = (rl < rmax) ? g_maskT[w * PRE_K + r0 + rl] : 0u;
        }
        if (tid < 32) sm.se.sbox[tid] = (tid < rmax) ? g_top[r0 + tid]
                                                     : make_float4(0.f, 0.f, 0.f, 0.f);
        __syncthreads();

        for (int rl = 0; rl < rmax; rl++) {
            int i = r0 + rl;
            bool keep = ((sm.se.svalid[i >> 5] >> (i & 31)) & 1u) &&
                        !((sm.se.sup[i >> 5] >> (i & 31)) & 1u);
            if (keep) {
                if (tid == 0) ((float4*)out)[kept] = sm.se.sbox[rl];
                if (tid < NW) sm.se.sup[tid] |= sm.se.cm[rl * NW + tid];
                __syncthreads();
                kept++;
                if (kept >= POST_K) break;
            }
        }
        __syncthreads();
    }

    for (int idx = tid; idx < (POST_K - kept) * 4; idx += BLK)
        out[kept * 4 + idx] = 0.f;
}

// ---------------- launcher ----------------
extern "C" void kernel_launch(void* const* d_in, const int* in_sizes, int n_in,
                              void* d_out, int out_size) {
    const float* pred_cls = (const float*)d_in[0];
    const float* pred_reg = (const float*)d_in[1];
    const float* anchor   = (const float*)d_in[2];
    float* out = (float*)d_out;

    init_kernel<<<296, 256>>>();
    mega_kernel<<<GRID, BLK>>>(pred_cls, pred_reg, anchor, out);
}

// round 7
// speedup vs baseline: 1.9499x; 1.7286x over previous
#include <cuda_runtime.h>
#include <cuda_bf16.h>
#include <math.h>

#define NN 90000
#define PRE_K 6000
#define POST_K 300
#define NW 188                    // ceil(6000/32)
#define NBINS 65536
#define CAND_CAP 8192
#define MIN_SIZE 0.02f
#define GRID 148
#define BLK 1024
#define STRIDE (GRID * BLK)
#define NSEG 16
#define SEG (CAND_CAP / NSEG)     // 512
#define CBX (CAND_CAP / BLK)      // 8 candidate x-units
#define NBATCH (PRE_K / 32)       // 188 wait: 6000/32 = 187.5 -> use NW

// ---------------- device scratch ----------------
__device__ unsigned long long g_keys[NN];
__device__ float4             g_boxes[NN];
__device__ unsigned int       g_hist[NBINS];
__device__ unsigned long long g_cand[CAND_CAP];
__device__ int                g_cand_cnt;
__device__ unsigned int       g_thresh;
__device__ int                g_rank[CAND_CAP];
__device__ float4             g_top[PRE_K + 32];
__device__ unsigned int       g_valid[NW];
__device__ unsigned int       g_barrier;

// ---------------- software grid barrier (148 blocks, all co-resident) ------
__device__ __forceinline__ void gsync(unsigned int target) {
    __syncthreads();
    if (threadIdx.x == 0) {
        __threadfence();
        atomicAdd(&g_barrier, 1u);
        volatile unsigned int* p = &g_barrier;
        while (*p < target) __nanosleep(64);
        __threadfence();
    }
    __syncthreads();
}

// ---------------- init kernel ----------------
__global__ void init_kernel() {
    int i = blockIdx.x * blockDim.x + threadIdx.x;
    for (int b = i; b < NBINS; b += 296 * 256) g_hist[b] = 0u;
    if (i < CAND_CAP) g_rank[i] = 0;
    if (i < NW) g_valid[i] = 0u;
    if (i == 0) { g_cand_cnt = 0; g_barrier = 0u; }
}

// ---------------- mega kernel ----------------
__global__ void __launch_bounds__(BLK, 1) mega_kernel(
        const float* __restrict__ pred_cls,
        const float* __restrict__ pred_reg,
        const float* __restrict__ anchor,
        float* __restrict__ out) {
    int tid = threadIdx.x;
    int bid = blockIdx.x;
    int gtid = bid * BLK + tid;

    __shared__ union {
        struct {                                    // thresh
            unsigned int part[BLK];
            unsigned int fine[64];
            int pt;
            unsigned int acc0;
        } th;
        unsigned long long tile[SEG];               // rank
        struct {                                    // batch NMS
            float4 kbox[POST_K];
            float  karea[POST_K];
            float4 bbox[32];
            float  barea[32];
            unsigned int mrow[32];
            unsigned int supA;
            unsigned int keepm;
            unsigned int validw;
            int kept;
        } nm;
    } sm;

    // ---------- phase 1: decode ----------
    for (int n = gtid; n < NN; n += STRIDE) {
        float4 a = *(const float4*)&anchor[n * 4];
        float4 r = *(const float4*)&pred_reg[n * 4];
        float acx = (a.x + a.z) * 0.5f;
        float acy = (a.y + a.w) * 0.5f;
        float aw  = a.z - a.x;
        float ah  = a.w - a.y;
        float cx = r.x * aw + acx;
        float cy = r.y * ah + acy;
        float w  = expf(r.z) * aw;
        float h  = expf(r.w) * ah;
        float x0 = fminf(fmaxf(cx - w * 0.5f, 0.f), 1.f);
        float y0 = fminf(fmaxf(cy - h * 0.5f, 0.f), 1.f);
        float x1 = fminf(fmaxf(cx + w * 0.5f, 0.f), 1.f);
        float y1 = fminf(fmaxf(cy + h * 0.5f, 0.f), 1.f);
        g_boxes[n] = make_float4(x0, y0, x1, y1);

        float l0 = pred_cls[2 * n];
        float l1 = pred_cls[2 * n + 1];
        float m  = fmaxf(l0, l1);
        float e0 = expf(l0 - m);
        float e1 = expf(l1 - m);
        float p  = e1 / (e0 + e1);
        bool size_ok = ((y1 - y0) >= MIN_SIZE) && ((x1 - x0) >= MIN_SIZE);
        float s = size_ok ? p : -INFINITY;
        unsigned int ub = __float_as_uint(s);
        unsigned int ordered = (ub & 0x80000000u) ? ~ub : (ub | 0x80000000u);
        unsigned long long key =
            ((unsigned long long)ordered << 17) | ((~(unsigned int)n) & 0x1FFFFu);
        g_keys[n] = key;
        atomicAdd(&g_hist[ordered >> 16], 1u);
    }
    gsync(1 * GRID);

    // ---------- phase 2: threshold (block 0) ----------
    if (bid == 0) {
        unsigned int s = 0;
        int base = tid * (NBINS / BLK);             // 64 bins per thread
        #pragma unroll 4
        for (int b = 0; b < NBINS / BLK; b++) s += g_hist[base + b];
        sm.th.part[tid] = s;
        __syncthreads();
        for (int off = 1; off < BLK; off <<= 1) {   // suffix scan
            unsigned int v = (tid + off < BLK) ? sm.th.part[tid + off] : 0u;
            __syncthreads();
            sm.th.part[tid] += v;
            __syncthreads();
        }
        bool pred = sm.th.part[tid] >= (unsigned)PRE_K;
        bool next = (tid < BLK - 1) ? (sm.th.part[tid + 1] >= (unsigned)PRE_K) : false;
        if (tid == 0) { sm.th.pt = 0; sm.th.acc0 = 0u; }
        __syncthreads();
        if (pred && !next) {
            sm.th.pt = tid;
            sm.th.acc0 = (tid < BLK - 1) ? sm.th.part[tid + 1] : 0u;
        }
        __syncthreads();
        int pt = sm.th.pt;
        unsigned int acc0 = sm.th.acc0;
        if (tid < 64) sm.th.fine[tid] = g_hist[pt * 64 + tid];
        __syncthreads();
        for (int off = 1; off < 64; off <<= 1) {
            unsigned int v = (tid < 64 && tid + off < 64) ? sm.th.fine[tid + off] : 0u;
            __syncthreads();
            if (tid < 64) sm.th.fine[tid] += v;
            __syncthreads();
        }
        if (tid < 64) {
            bool fp = (acc0 + sm.th.fine[tid]) >= (unsigned)PRE_K;
            bool fn = (tid < 63) ? ((acc0 + sm.th.fine[tid + 1]) >= (unsigned)PRE_K) : false;
            if (fp && !fn) g_thresh = (unsigned int)(pt * 64 + tid);
        }
    }
    gsync(2 * GRID);

    // ---------- phase 3: compact ----------
    {
        unsigned int T = g_thresh;
        for (int n = gtid; n < NN; n += STRIDE) {
            unsigned long long key = g_keys[n];
            if ((unsigned int)(key >> 33) >= T) {
                int p = atomicAdd(&g_cand_cnt, 1);
                if (p < CAND_CAP) g_cand[p] = key;
            }
        }
    }
    gsync(3 * GRID);

    // ---------- phase 4: rank by counting (keys unique) ----------
    {
        int C = g_cand_cnt; if (C > CAND_CAP) C = CAND_CAP;
        for (int unit = bid; unit < CBX * NSEG; unit += GRID) {
            int bx  = unit / NSEG;
            int seg = unit % NSEG;
            int c   = bx * BLK + tid;
            unsigned long long kc = (c < C) ? g_cand[c] : 0xFFFFFFFFFFFFFFFFULL;
            __syncthreads();
            if (tid < SEG) {
                int gi = seg * SEG + tid;
                sm.tile[tid] = (gi < C) ? g_cand[gi] : 0ULL;
            }
            __syncthreads();
            int cnt = 0;
            #pragma unroll 8
            for (int k = 0; k < SEG; k++)
                cnt += (sm.tile[k] > kc);
            if (c < C && cnt) atomicAdd(&g_rank[c], cnt);
        }
    }
    gsync(4 * GRID);

    // ---------- phase 5: scatter ----------
    {
        int C = g_cand_cnt; if (C > CAND_CAP) C = CAND_CAP;
        for (int c = gtid; c < C; c += STRIDE) {
            int rank = g_rank[c];
            if (rank >= PRE_K) continue;
            unsigned long long key = g_cand[c];
            unsigned int idx = (~(unsigned int)key) & 0x1FFFFu;
            float4 b = (idx < NN) ? g_boxes[idx] : make_float4(0.f, 0.f, 0.f, 0.f);
            g_top[rank] = b;
            if ((key >> 48) & 1ULL)
                atomicOr(&g_valid[rank >> 5], 1u << (rank & 31));
        }
    }
    gsync(5 * GRID);

    // ---------- phase 6: batched greedy NMS (block 0 only) ----------
    if (bid != 0) return;

    int lane = tid & 31;
    int wrp  = tid >> 5;

    if (tid == 0) sm.nm.kept = 0;
    __syncthreads();

    for (int c = 0; c < NW; c++) {
        int keptC = sm.nm.kept;
        if (keptC >= POST_K) break;
        int r0 = c * 32;

        // stage 1: load batch
        if (tid < 32) {
            int r = r0 + tid;
            float4 b = (r < PRE_K) ? g_top[r] : make_float4(0.f, 0.f, 0.f, 0.f);
            sm.nm.bbox[tid]  = b;
            sm.nm.barea[tid] = (b.z - b.x) * (b.w - b.y);
        }
        if (tid == 0) {
            sm.nm.supA   = 0u;
            sm.nm.validw = g_valid[c];
        }
        __syncthreads();

        // stage A: suppression by existing kept list
        // warp w covers kept indices {w, w+32, ...}; lane j = candidate
        {
            float4 bj = sm.nm.bbox[lane];
            float  aj = sm.nm.barea[lane];
            bool supped = false;
            for (int k = wrp; k < keptC; k += 32) {
                float4 bk = sm.nm.kbox[k];
                float x0 = fmaxf(bk.x, bj.x);
                float y0 = fmaxf(bk.y, bj.y);
                float x1 = fminf(bk.z, bj.z);
                float y1 = fminf(bk.w, bj.w);
                float iw = fmaxf(x1 - x0, 0.f);
                float ih = fmaxf(y1 - y0, 0.f);
                float inter = iw * ih;
                float uni   = sm.nm.karea[k] + aj - inter;
                if (inter / fmaxf(uni, 1e-12f) > 0.7f) { supped = true; break; }
            }
            unsigned int bal = __ballot_sync(0xFFFFFFFFu, supped);
            if (lane == 0 && bal) atomicOr(&sm.nm.supA, bal);
        }

        // stage B: in-batch 32x32 IoU matrix; warp w = row i, lane = col j
        {
            float4 bi = sm.nm.bbox[wrp];
            float  ai = sm.nm.barea[wrp];
            float4 bj = sm.nm.bbox[lane];
            float x0 = fmaxf(bi.x, bj.x);
            float y0 = fmaxf(bi.y, bj.y);
            float x1 = fminf(bi.z, bj.z);
            float y1 = fminf(bi.w, bj.w);
            float iw = fmaxf(x1 - x0, 0.f);
            float ih = fmaxf(y1 - y0, 0.f);
            float inter = iw * ih;
            float uni   = ai + sm.nm.barea[lane] - inter;
            bool bit = (inter / fmaxf(uni, 1e-12f) > 0.7f) && (lane > wrp);
            unsigned int bal = __ballot_sync(0xFFFFFFFFu, bit);
            if (lane == 0) sm.nm.mrow[wrp] = bal;
        }
        __syncthreads();

        // stage C: resolve batch greedily (thread 0)
        if (tid == 0) {
            unsigned int sup = sm.nm.supA | ~sm.nm.validw;
            unsigned int keepm = 0;
            #pragma unroll
            for (int i = 0; i < 32; i++) {
                if (!((sup >> i) & 1u)) {
                    keepm |= (1u << i);
                    sup |= sm.nm.mrow[i];
                }
            }
            sm.nm.keepm = keepm;
            sm.nm.kept  = keptC + __popc(keepm);
        }
        __syncthreads();

        // stage D: append kept boxes (output + kept list)
        if (tid < 32) {
            unsigned int keepm = sm.nm.keepm;
            if ((keepm >> tid) & 1u) {
                int pos = keptC + __popc(keepm & ((1u << tid) - 1u));
                if (pos < POST_K) {
                    float4 b = sm.nm.bbox[tid];
                    sm.nm.kbox[pos]  = b;
                    sm.nm.karea[pos] = sm.nm.barea[tid];
                    ((float4*)out)[pos] = b;
                }
            }
        }
        __syncthreads();
    }

    // zero-fill remaining output
    int kept = sm.nm.kept;
    if (kept > POST_K) kept = POST_K;
    for (int idx = tid; idx < (POST_K - kept) * 4; idx += BLK)
        out[kept * 4 + idx] = 0.f;
}

// ---------------- launcher ----------------
extern "C" void kernel_launch(void* const* d_in, const int* in_sizes, int n_in,
                              void* d_out, int out_size) {
    const float* pred_cls = (const float*)d_in[0];
    const float* pred_reg = (const float*)d_in[1];
    const float* anchor   = (const float*)d_in[2];
    float* out = (float*)d_out;

    init_kernel<<<296, 256>>>();
    mega_kernel<<<GRID, BLK>>>(pred_cls, pred_reg, anchor, out);
}